// round 1
// baseline (speedup 1.0000x reference)
#include <cuda_runtime.h>

// Problem constants
#define NB  8
#define C   256
#define G   8
#define KPT 9
#define H   64
#define W   64
#define L   (H * W)          // 4096
#define JOM (G * KPT * 3)    // 216
#define CG  (C / G)          // 32

// Scratch buffers (static device memory; no allocations anywhere)
__device__ float g_om_in[(size_t)NB * C * L];     // depthwise conv output, (n, c, l)
__device__ float g_value[(size_t)NB * L * C];     // value projection,      (n, l, c)
__device__ float g_om[(size_t)NB * L * JOM];      // offset/mask,           (n, l, 216)
__device__ float g_sampled[(size_t)NB * L * C];   // sampled values,        (n, l, c)

// ---------------------------------------------------------------------------
// Depthwise 3x3 conv, SAME padding (cross-correlation, matching lax.conv).
// x: (n, c, h, w) -> g_om_in (n, c, l)
// ---------------------------------------------------------------------------
__global__ __launch_bounds__(256) void dwconv_kernel(const float* __restrict__ x,
                                                     const float* __restrict__ w,
                                                     const float* __restrict__ b) {
    int l = blockIdx.x * 256 + threadIdx.x;
    int c = blockIdx.y;
    int n = blockIdx.z;
    int yy = l >> 6, xx = l & 63;
    const float* xp = x + ((size_t)n * C + c) * L;
    const float* wp = w + c * 9;
    float acc = b[c];
#pragma unroll
    for (int dy = -1; dy <= 1; dy++) {
#pragma unroll
        for (int dx = -1; dx <= 1; dx++) {
            int y2 = yy + dy, x2 = xx + dx;
            if (y2 >= 0 && y2 < H && x2 >= 0 && x2 < W)
                acc += wp[(dy + 1) * 3 + (dx + 1)] * xp[y2 * W + x2];
        }
    }
    g_om_in[((size_t)n * C + c) * L + l] = acc;
}

// ---------------------------------------------------------------------------
// GEMM type 1: out[n][l][j] = sum_c X[n][c][l] * Wt[j][c] + bias[j]
// X is (n, C, L) "NCHW-flat" (contiguous in l). Wt is (J, C) row-major.
// 128x128 tile, BK=8, 256 threads, 8x8 micro-tile, reg-prefetch pipeline.
// ---------------------------------------------------------------------------
__global__ __launch_bounds__(256) void gemm_xw_kernel(const float* __restrict__ X,
                                                      const float* __restrict__ Wt,
                                                      const float* __restrict__ bias,
                                                      float* __restrict__ out,
                                                      int J) {
    __shared__ float As[8][128];
    __shared__ float Bs[8][132];   // padded row: conflict-free transposed stores

    int n  = blockIdx.z;
    int m0 = blockIdx.y * 128;     // l tile
    int n0 = blockIdx.x * 128;     // j tile
    int tid = threadIdx.x;
    int tx = tid & 15, ty = tid >> 4;

    const float* A = X + (size_t)n * C * L;

    // A tile load mapping: 8 rows (c) x 128 cols (l), one float4 per thread
    int akk = tid >> 5;
    int amm = (tid & 31) << 2;
    // B tile load mapping: 128 rows (j) x 8 cols (c), one float4 per thread
    int bj = tid >> 1;
    int bc = (tid & 1) << 2;

    float4 areg = *(const float4*)(A + (size_t)akk * L + m0 + amm);
    float4 breg = make_float4(0.f, 0.f, 0.f, 0.f);
    if (n0 + bj < J) breg = *(const float4*)(Wt + (size_t)(n0 + bj) * C + bc);

    float acc[8][8];
#pragma unroll
    for (int i = 0; i < 8; i++)
#pragma unroll
        for (int j = 0; j < 8; j++) acc[i][j] = 0.f;

    for (int kt = 0; kt < C; kt += 8) {
        *(float4*)&As[akk][amm] = areg;
        Bs[bc + 0][bj] = breg.x;
        Bs[bc + 1][bj] = breg.y;
        Bs[bc + 2][bj] = breg.z;
        Bs[bc + 3][bj] = breg.w;
        __syncthreads();

        if (kt + 8 < C) {
            areg = *(const float4*)(A + (size_t)(kt + 8 + akk) * L + m0 + amm);
            if (n0 + bj < J)
                breg = *(const float4*)(Wt + (size_t)(n0 + bj) * C + kt + 8 + bc);
        }

#pragma unroll
        for (int kk = 0; kk < 8; kk++) {
            float a[8], b[8];
            *(float4*)(a)     = *(const float4*)&As[kk][ty * 8];
            *(float4*)(a + 4) = *(const float4*)&As[kk][ty * 8 + 4];
            *(float4*)(b)     = *(const float4*)&Bs[kk][tx * 8];
            *(float4*)(b + 4) = *(const float4*)&Bs[kk][tx * 8 + 4];
#pragma unroll
            for (int i = 0; i < 8; i++)
#pragma unroll
                for (int j = 0; j < 8; j++) acc[i][j] += a[i] * b[j];
        }
        __syncthreads();
    }

    int jb = n0 + tx * 8;
    if (jb < J) {
        float4 bb0 = *(const float4*)(bias + jb);
        float4 bb1 = *(const float4*)(bias + jb + 4);
        float* outp = out + (size_t)n * L * J;
#pragma unroll
        for (int i = 0; i < 8; i++) {
            int row = m0 + ty * 8 + i;
            float* o = outp + (size_t)row * J + jb;
            float4 v0 = make_float4(acc[i][0] + bb0.x, acc[i][1] + bb0.y,
                                    acc[i][2] + bb0.z, acc[i][3] + bb0.w);
            float4 v1 = make_float4(acc[i][4] + bb1.x, acc[i][5] + bb1.y,
                                    acc[i][6] + bb1.z, acc[i][7] + bb1.w);
            *(float4*)o       = v0;
            *(float4*)(o + 4) = v1;
        }
    }
}

// ---------------------------------------------------------------------------
// GEMM type 2 (output projection, writes NCHW directly):
// out[n][m][l] = sum_c Wm[m][c] * S[n][l][c]
// Wm (C, C) row-major, S (n, L, C) row-major. out row stride L.
// ---------------------------------------------------------------------------
__global__ __launch_bounds__(256) void gemm_out_kernel(const float* __restrict__ Wm,
                                                       const float* __restrict__ S,
                                                       float* __restrict__ out) {
    __shared__ float As[8][132];
    __shared__ float Bs[8][132];

    int n  = blockIdx.z;
    int m0 = blockIdx.y * 128;   // cout tile
    int n0 = blockIdx.x * 128;   // l tile
    int tid = threadIdx.x;
    int tx = tid & 15, ty = tid >> 4;

    const float* Sb = S + (size_t)n * L * C;

    int rr = tid >> 1;          // row within tile (m for A, l for B)
    int cc = (tid & 1) << 2;    // c offset

    float4 areg = *(const float4*)(Wm + (size_t)(m0 + rr) * C + cc);
    float4 breg = *(const float4*)(Sb + (size_t)(n0 + rr) * C + cc);

    float acc[8][8];
#pragma unroll
    for (int i = 0; i < 8; i++)
#pragma unroll
        for (int j = 0; j < 8; j++) acc[i][j] = 0.f;

    for (int kt = 0; kt < C; kt += 8) {
        As[cc + 0][rr] = areg.x;
        As[cc + 1][rr] = areg.y;
        As[cc + 2][rr] = areg.z;
        As[cc + 3][rr] = areg.w;
        Bs[cc + 0][rr] = breg.x;
        Bs[cc + 1][rr] = breg.y;
        Bs[cc + 2][rr] = breg.z;
        Bs[cc + 3][rr] = breg.w;
        __syncthreads();

        if (kt + 8 < C) {
            areg = *(const float4*)(Wm + (size_t)(m0 + rr) * C + kt + 8 + cc);
            breg = *(const float4*)(Sb + (size_t)(n0 + rr) * C + kt + 8 + cc);
        }

#pragma unroll
        for (int kk = 0; kk < 8; kk++) {
            float a[8], b[8];
            *(float4*)(a)     = *(const float4*)&As[kk][ty * 8];
            *(float4*)(a + 4) = *(const float4*)&As[kk][ty * 8 + 4];
            *(float4*)(b)     = *(const float4*)&Bs[kk][tx * 8];
            *(float4*)(b + 4) = *(const float4*)&Bs[kk][tx * 8 + 4];
#pragma unroll
            for (int i = 0; i < 8; i++)
#pragma unroll
                for (int j = 0; j < 8; j++) acc[i][j] += a[i] * b[j];
        }
        __syncthreads();
    }

#pragma unroll
    for (int i = 0; i < 8; i++) {
        float* o = out + ((size_t)n * C + m0 + ty * 8 + i) * L + n0 + tx * 8;
        *(float4*)o       = make_float4(acc[i][0], acc[i][1], acc[i][2], acc[i][3]);
        *(float4*)(o + 4) = make_float4(acc[i][4], acc[i][5], acc[i][6], acc[i][7]);
    }
}

// ---------------------------------------------------------------------------
// Deformable bilinear sampling.
// One warp per (n, g, l); lane = cg channel. Warps ordered (n, g, l) so
// adjacent warps hit overlapping taps (L1 reuse). Gathers are 128B coalesced.
// ---------------------------------------------------------------------------
__global__ __launch_bounds__(256) void sample_kernel() {
    int wid  = (blockIdx.x * 256 + threadIdx.x) >> 5;
    int lane = threadIdx.x & 31;
    int l = wid & (L - 1);
    int g = (wid >> 12) & (G - 1);
    int n = wid >> 15;
    int yy = l >> 6, xx = l & 63;

    const float* omp   = g_om + (size_t)(n * L + l) * JOM + g * 27;
    const float* vbase = g_value + (size_t)n * L * C + g * CG + lane;

    float acc = 0.f;
#pragma unroll
    for (int k = 0; k < KPT; k++) {
        float oy = omp[2 * k];
        float ox = omp[2 * k + 1];
        float mw = omp[18 + k];
        float py = (float)(yy + (k / 3) - 1) + oy;
        float px = (float)(xx + (k % 3) - 1) + ox;
        float y0f = floorf(py), x0f = floorf(px);
        float tyf = py - y0f, txf = px - x0f;
        int y0 = (int)y0f, x0 = (int)x0f;
        int y1 = y0 + 1, x1 = x0 + 1;

        float w00 = (1.f - tyf) * (1.f - txf);
        float w01 = (1.f - tyf) * txf;
        float w10 = tyf * (1.f - txf);
        float w11 = tyf * txf;

        bool vy0 = (y0 >= 0) && (y0 < H);
        bool vy1 = (y1 >= 0) && (y1 < H);
        bool vx0 = (x0 >= 0) && (x0 < W);
        bool vx1 = (x1 >= 0) && (x1 < W);

        int y0c = min(max(y0, 0), H - 1);
        int y1c = min(max(y1, 0), H - 1);
        int x0c = min(max(x0, 0), W - 1);
        int x1c = min(max(x1, 0), W - 1);

        float v00 = vbase[(size_t)(y0c * W + x0c) * C];
        float v01 = vbase[(size_t)(y0c * W + x1c) * C];
        float v10 = vbase[(size_t)(y1c * W + x0c) * C];
        float v11 = vbase[(size_t)(y1c * W + x1c) * C];

        float s = 0.f;
        if (vy0 && vx0) s += w00 * v00;
        if (vy0 && vx1) s += w01 * v01;
        if (vy1 && vx0) s += w10 * v10;
        if (vy1 && vx1) s += w11 * v11;
        acc += mw * s;
    }

    g_sampled[(size_t)(n * L + l) * C + g * CG + lane] = acc;
}

// ---------------------------------------------------------------------------
// Launch: dwconv -> om GEMM -> value GEMM -> sampler -> output GEMM
// ---------------------------------------------------------------------------
extern "C" void kernel_launch(void* const* d_in, const int* in_sizes, int n_in,
                              void* d_out, int out_size) {
    const float* x    = (const float*)d_in[0];
    const float* dw_w = (const float*)d_in[1];
    const float* dw_b = (const float*)d_in[2];
    const float* om_w = (const float*)d_in[3];
    const float* om_b = (const float*)d_in[4];
    const float* vp_w = (const float*)d_in[5];
    const float* vp_b = (const float*)d_in[6];
    const float* op_w = (const float*)d_in[7];
    float* out = (float*)d_out;

    float *p_om_in, *p_value, *p_om, *p_sampled;
    cudaGetSymbolAddress((void**)&p_om_in, g_om_in);
    cudaGetSymbolAddress((void**)&p_value, g_value);
    cudaGetSymbolAddress((void**)&p_om, g_om);
    cudaGetSymbolAddress((void**)&p_sampled, g_sampled);

    dwconv_kernel<<<dim3(L / 256, C, NB), 256>>>(x, dw_w, dw_b);
    gemm_xw_kernel<<<dim3(2, L / 128, NB), 256>>>(p_om_in, om_w, om_b, p_om, JOM);
    gemm_xw_kernel<<<dim3(2, L / 128, NB), 256>>>(x, vp_w, vp_b, p_value, C);
    sample_kernel<<<(NB * G * L) / 8, 256>>>();
    gemm_out_kernel<<<dim3(L / 128, 2, NB), 256>>>(op_w, p_sampled, out);
}

// round 2
// speedup vs baseline: 1.1561x; 1.1561x over previous
#include <cuda_runtime.h>

// Problem constants
#define NB  8
#define C   256
#define G   8
#define KPT 9
#define H   64
#define W   64
#define L   (H * W)          // 4096
#define JOM (G * KPT * 3)    // 216
#define CG  (C / G)          // 32

// Scratch buffers (static device memory; no allocations anywhere)
__device__ float g_om_in[(size_t)NB * C * L];     // depthwise conv output, (n, c, l)
__device__ float g_value[(size_t)NB * L * C];     // value projection,      (n, l, c)
__device__ float g_om[(size_t)NB * L * JOM];      // offset/mask,           (n, l, 216)
__device__ float g_sampled[(size_t)NB * L * C];   // sampled values,        (n, l, c)

// ---------------------------------------------------------------------------
// Depthwise 3x3 conv, SAME padding (cross-correlation, matching lax.conv).
// ---------------------------------------------------------------------------
__global__ __launch_bounds__(256) void dwconv_kernel(const float* __restrict__ x,
                                                     const float* __restrict__ w,
                                                     const float* __restrict__ b) {
    int l = blockIdx.x * 256 + threadIdx.x;
    int c = blockIdx.y;
    int n = blockIdx.z;
    int yy = l >> 6, xx = l & 63;
    const float* xp = x + (n * C + c) * L;
    const float* wp = w + c * 9;
    float acc = b[c];
#pragma unroll
    for (int dy = -1; dy <= 1; dy++) {
#pragma unroll
        for (int dx = -1; dx <= 1; dx++) {
            int y2 = yy + dy, x2 = xx + dx;
            if (y2 >= 0 && y2 < H && x2 >= 0 && x2 < W)
                acc += wp[(dy + 1) * 3 + (dx + 1)] * xp[y2 * W + x2];
        }
    }
    g_om_in[(n * C + c) * L + l] = acc;
}

// ---------------------------------------------------------------------------
// GEMM type 1: out[n][l][j] = sum_c X[n][c][l] * Wt[j][c] + bias[j]
// Double-buffered smem, one __syncthreads per k-tile, 32-bit indexing.
// ---------------------------------------------------------------------------
__global__ __launch_bounds__(256) void gemm_xw_kernel(const float* __restrict__ X,
                                                      const float* __restrict__ Wt,
                                                      const float* __restrict__ bias,
                                                      float* __restrict__ out,
                                                      int J) {
    __shared__ float As[2][8][128];
    __shared__ float Bs[2][8][132];

    int n  = blockIdx.z;
    int m0 = blockIdx.y * 128;     // l tile
    int n0 = blockIdx.x * 128;     // j tile
    int tid = threadIdx.x;
    int tx = tid & 15, ty = tid >> 4;

    const float* A = X + n * C * L;

    int akk = tid >> 5;
    int amm = (tid & 31) << 2;
    int bj = tid >> 1;
    int bc = (tid & 1) << 2;
    bool bvalid = (n0 + bj) < J;

    float4 areg = *(const float4*)(A + akk * L + m0 + amm);
    float4 breg = make_float4(0.f, 0.f, 0.f, 0.f);
    if (bvalid) breg = *(const float4*)(Wt + (n0 + bj) * C + bc);

    float acc[8][8];
#pragma unroll
    for (int i = 0; i < 8; i++)
#pragma unroll
        for (int j = 0; j < 8; j++) acc[i][j] = 0.f;

    // prologue: store tile 0 into buffer 0
    *(float4*)&As[0][akk][amm] = areg;
    Bs[0][bc + 0][bj] = breg.x;
    Bs[0][bc + 1][bj] = breg.y;
    Bs[0][bc + 2][bj] = breg.z;
    Bs[0][bc + 3][bj] = breg.w;
    __syncthreads();

    for (int kt = 0; kt < C; kt += 8) {
        int buf = (kt >> 3) & 1;
        bool more = (kt + 8) < C;
        if (more) {
            areg = *(const float4*)(A + (kt + 8 + akk) * L + m0 + amm);
            if (bvalid) breg = *(const float4*)(Wt + (n0 + bj) * C + kt + 8 + bc);
        }
#pragma unroll
        for (int kk = 0; kk < 8; kk++) {
            float a[8], b[8];
            *(float4*)(a)     = *(const float4*)&As[buf][kk][ty * 8];
            *(float4*)(a + 4) = *(const float4*)&As[buf][kk][ty * 8 + 4];
            *(float4*)(b)     = *(const float4*)&Bs[buf][kk][tx * 8];
            *(float4*)(b + 4) = *(const float4*)&Bs[buf][kk][tx * 8 + 4];
#pragma unroll
            for (int i = 0; i < 8; i++)
#pragma unroll
                for (int j = 0; j < 8; j++) acc[i][j] += a[i] * b[j];
        }
        if (more) {
            int nb = buf ^ 1;
            *(float4*)&As[nb][akk][amm] = areg;
            Bs[nb][bc + 0][bj] = breg.x;
            Bs[nb][bc + 1][bj] = breg.y;
            Bs[nb][bc + 2][bj] = breg.z;
            Bs[nb][bc + 3][bj] = breg.w;
            __syncthreads();
        }
    }

    int jb = n0 + tx * 8;
    if (jb < J) {
        float4 bb0 = *(const float4*)(bias + jb);
        float4 bb1 = *(const float4*)(bias + jb + 4);
        float* outp = out + n * L * J;
#pragma unroll
        for (int i = 0; i < 8; i++) {
            int row = m0 + ty * 8 + i;
            float* o = outp + row * J + jb;
            *(float4*)o       = make_float4(acc[i][0] + bb0.x, acc[i][1] + bb0.y,
                                            acc[i][2] + bb0.z, acc[i][3] + bb0.w);
            *(float4*)(o + 4) = make_float4(acc[i][4] + bb1.x, acc[i][5] + bb1.y,
                                            acc[i][6] + bb1.z, acc[i][7] + bb1.w);
        }
    }
}

// ---------------------------------------------------------------------------
// GEMM type 2 (output projection, writes NCHW directly):
// out[n][m][l] = sum_c Wm[m][c] * S[n][l][c]
// ---------------------------------------------------------------------------
__global__ __launch_bounds__(256) void gemm_out_kernel(const float* __restrict__ Wm,
                                                       const float* __restrict__ S,
                                                       float* __restrict__ out) {
    __shared__ float As[2][8][132];
    __shared__ float Bs[2][8][132];

    int n  = blockIdx.z;
    int m0 = blockIdx.y * 128;   // cout tile
    int n0 = blockIdx.x * 128;   // l tile
    int tid = threadIdx.x;
    int tx = tid & 15, ty = tid >> 4;

    const float* Sb = S + n * L * C;

    int rr = tid >> 1;
    int cc = (tid & 1) << 2;

    float4 areg = *(const float4*)(Wm + (m0 + rr) * C + cc);
    float4 breg = *(const float4*)(Sb + (n0 + rr) * C + cc);

    float acc[8][8];
#pragma unroll
    for (int i = 0; i < 8; i++)
#pragma unroll
        for (int j = 0; j < 8; j++) acc[i][j] = 0.f;

    As[0][cc + 0][rr] = areg.x;
    As[0][cc + 1][rr] = areg.y;
    As[0][cc + 2][rr] = areg.z;
    As[0][cc + 3][rr] = areg.w;
    Bs[0][cc + 0][rr] = breg.x;
    Bs[0][cc + 1][rr] = breg.y;
    Bs[0][cc + 2][rr] = breg.z;
    Bs[0][cc + 3][rr] = breg.w;
    __syncthreads();

    for (int kt = 0; kt < C; kt += 8) {
        int buf = (kt >> 3) & 1;
        bool more = (kt + 8) < C;
        if (more) {
            areg = *(const float4*)(Wm + (m0 + rr) * C + kt + 8 + cc);
            breg = *(const float4*)(Sb + (n0 + rr) * C + kt + 8 + cc);
        }
#pragma unroll
        for (int kk = 0; kk < 8; kk++) {
            float a[8], b[8];
            *(float4*)(a)     = *(const float4*)&As[buf][kk][ty * 8];
            *(float4*)(a + 4) = *(const float4*)&As[buf][kk][ty * 8 + 4];
            *(float4*)(b)     = *(const float4*)&Bs[buf][kk][tx * 8];
            *(float4*)(b + 4) = *(const float4*)&Bs[buf][kk][tx * 8 + 4];
#pragma unroll
            for (int i = 0; i < 8; i++)
#pragma unroll
                for (int j = 0; j < 8; j++) acc[i][j] += a[i] * b[j];
        }
        if (more) {
            int nb = buf ^ 1;
            As[nb][cc + 0][rr] = areg.x;
            As[nb][cc + 1][rr] = areg.y;
            As[nb][cc + 2][rr] = areg.z;
            As[nb][cc + 3][rr] = areg.w;
            Bs[nb][cc + 0][rr] = breg.x;
            Bs[nb][cc + 1][rr] = breg.y;
            Bs[nb][cc + 2][rr] = breg.z;
            Bs[nb][cc + 3][rr] = breg.w;
            __syncthreads();
        }
    }

#pragma unroll
    for (int i = 0; i < 8; i++) {
        float* o = out + (n * C + m0 + ty * 8 + i) * L + n0 + tx * 8;
        *(float4*)o       = make_float4(acc[i][0], acc[i][1], acc[i][2], acc[i][3]);
        *(float4*)(o + 4) = make_float4(acc[i][4], acc[i][5], acc[i][6], acc[i][7]);
    }
}

// ---------------------------------------------------------------------------
// Deformable bilinear sampling, v2.
// Thread layout: c4 = tid&7 (float4 of channels, 8 threads cover cg=32),
// li = tid>>3 (32 spatial positions per block). Grid (L/32, G, NB).
// Per-tap scalar chain amortized over 4 channels; 32-bit indexing;
// om coefficients staged in smem; valid-masking by float multiply.
// ---------------------------------------------------------------------------
__global__ __launch_bounds__(256) void sample_kernel() {
    __shared__ float om_s[32][28];   // 27 coeffs + pad

    int tid = threadIdx.x;
    int c4 = tid & 7;
    int li = tid >> 3;
    int l0 = blockIdx.x * 32;
    int g  = blockIdx.y;
    int n  = blockIdx.z;

    // cooperative load of om coefficients for 32 positions of this group
    for (int i = tid; i < 32 * 27; i += 256) {
        int li2 = i / 27, j = i - li2 * 27;
        om_s[li2][j] = g_om[(n * L + l0 + li2) * JOM + g * 27 + j];
    }
    __syncthreads();

    int l = l0 + li;
    int yy = l >> 6, xx = l & 63;

    // base (in float4 units) of this batch/group's value plane
    const float4* __restrict__ vp =
        (const float4*)(g_value + n * L * C + g * CG) + c4;
    const float fyy = (float)yy, fxx = (float)xx;

    float4 acc = make_float4(0.f, 0.f, 0.f, 0.f);

#pragma unroll
    for (int k = 0; k < KPT; k++) {
        float oy = om_s[li][2 * k];
        float ox = om_s[li][2 * k + 1];
        float mw = om_s[li][18 + k];

        float py = fyy + (float)(k / 3 - 1) + oy;
        float px = fxx + (float)(k % 3 - 1) + ox;
        float y0f = floorf(py), x0f = floorf(px);
        float tyf = py - y0f, txf = px - x0f;
        int y0 = (int)y0f, x0 = (int)x0f;
        int y1 = y0 + 1, x1 = x0 + 1;

        float vy0 = (y0 >= 0 && y0 < H) ? 1.f : 0.f;
        float vy1 = (y1 >= 0 && y1 < H) ? 1.f : 0.f;
        float vx0 = (x0 >= 0 && x0 < W) ? 1.f : 0.f;
        float vx1 = (x1 >= 0 && x1 < W) ? 1.f : 0.f;

        float w00 = mw * (1.f - tyf) * (1.f - txf) * vy0 * vx0;
        float w01 = mw * (1.f - tyf) * txf * vy0 * vx1;
        float w10 = mw * tyf * (1.f - txf) * vy1 * vx0;
        float w11 = mw * tyf * txf * vy1 * vx1;

        int y0c = min(max(y0, 0), H - 1);
        int y1c = min(max(y1, 0), H - 1);
        int x0c = min(max(x0, 0), W - 1);
        int x1c = min(max(x1, 0), W - 1);

        // float4-unit row offsets: (y*64+x) * (C/4) = (y<<12) + (x<<6)
        int yA = y0c << 12, yB = y1c << 12;
        int xA = x0c << 6,  xB = x1c << 6;

        float4 v00 = __ldg(vp + (yA + xA));
        float4 v01 = __ldg(vp + (yA + xB));
        float4 v10 = __ldg(vp + (yB + xA));
        float4 v11 = __ldg(vp + (yB + xB));

        acc.x += w00 * v00.x + w01 * v01.x + w10 * v10.x + w11 * v11.x;
        acc.y += w00 * v00.y + w01 * v01.y + w10 * v10.y + w11 * v11.y;
        acc.z += w00 * v00.z + w01 * v01.z + w10 * v10.z + w11 * v11.z;
        acc.w += w00 * v00.w + w01 * v01.w + w10 * v10.w + w11 * v11.w;
    }

    *((float4*)(g_sampled + (n * L + l) * C + g * CG) + c4) = acc;
}

// ---------------------------------------------------------------------------
// Launch: dwconv -> om GEMM -> value GEMM -> sampler -> output GEMM
// ---------------------------------------------------------------------------
extern "C" void kernel_launch(void* const* d_in, const int* in_sizes, int n_in,
                              void* d_out, int out_size) {
    const float* x    = (const float*)d_in[0];
    const float* dw_w = (const float*)d_in[1];
    const float* dw_b = (const float*)d_in[2];
    const float* om_w = (const float*)d_in[3];
    const float* om_b = (const float*)d_in[4];
    const float* vp_w = (const float*)d_in[5];
    const float* vp_b = (const float*)d_in[6];
    const float* op_w = (const float*)d_in[7];
    float* out = (float*)d_out;

    float *p_om_in, *p_value, *p_om, *p_sampled;
    cudaGetSymbolAddress((void**)&p_om_in, g_om_in);
    cudaGetSymbolAddress((void**)&p_value, g_value);
    cudaGetSymbolAddress((void**)&p_om, g_om);
    cudaGetSymbolAddress((void**)&p_sampled, g_sampled);

    dwconv_kernel<<<dim3(L / 256, C, NB), 256>>>(x, dw_w, dw_b);
    gemm_xw_kernel<<<dim3(2, L / 128, NB), 256>>>(p_om_in, om_w, om_b, p_om, JOM);
    gemm_xw_kernel<<<dim3(2, L / 128, NB), 256>>>(x, vp_w, vp_b, p_value, C);
    sample_kernel<<<dim3(L / 32, G, NB), 256>>>();
    gemm_out_kernel<<<dim3(L / 128, 2, NB), 256>>>(op_w, p_sampled, out);
}

// round 3
// speedup vs baseline: 1.1769x; 1.0180x over previous
#include <cuda_runtime.h>
#include <cstdint>

// Problem constants
#define NB  8
#define C   256
#define G   8
#define KPT 9
#define H   64
#define W   64
#define L   (H * W)          // 4096
#define JOM (G * KPT * 3)    // 216
#define CG  (C / G)          // 32

// Scratch buffers (static device memory; no allocations anywhere)
__device__ float g_om_in[(size_t)NB * C * L];     // depthwise conv output, (n, c, l)
__device__ float g_value[(size_t)NB * L * C];     // value projection,      (n, l, c)
__device__ float g_om[(size_t)NB * L * JOM];      // offset/mask,           (n, l, 216)
__device__ float g_sampled[(size_t)NB * L * C];   // sampled values,        (n, l, c)

// ---- packed f32x2 helpers (Blackwell FFMA2 — ptxas never auto-fuses) ------
__device__ __forceinline__ void fma2(uint64_t& d, uint64_t a, uint64_t b) {
    asm("fma.rn.f32x2 %0, %1, %2, %0;" : "+l"(d) : "l"(a), "l"(b));
}
__device__ __forceinline__ uint64_t dup2(float a) {
    uint64_t r;
    asm("mov.b64 %0, {%1, %1};" : "=l"(r) : "f"(a));
    return r;
}
__device__ __forceinline__ float2 unpack2(uint64_t v) {
    float2 r;
    asm("mov.b64 {%0, %1}, %2;" : "=f"(r.x), "=f"(r.y) : "l"(v));
    return r;
}

// ---------------------------------------------------------------------------
// Depthwise 3x3 conv, SAME padding (cross-correlation, matching lax.conv).
// ---------------------------------------------------------------------------
__global__ __launch_bounds__(256) void dwconv_kernel(const float* __restrict__ x,
                                                     const float* __restrict__ w,
                                                     const float* __restrict__ b) {
    int l = blockIdx.x * 256 + threadIdx.x;
    int c = blockIdx.y;
    int n = blockIdx.z;
    int yy = l >> 6, xx = l & 63;
    const float* xp = x + (n * C + c) * L;
    const float* wp = w + c * 9;
    float acc = b[c];
#pragma unroll
    for (int dy = -1; dy <= 1; dy++) {
#pragma unroll
        for (int dx = -1; dx <= 1; dx++) {
            int y2 = yy + dy, x2 = xx + dx;
            if (y2 >= 0 && y2 < H && x2 >= 0 && x2 < W)
                acc += wp[(dy + 1) * 3 + (dx + 1)] * xp[y2 * W + x2];
        }
    }
    g_om_in[(n * C + c) * L + l] = acc;
}

// ---------------------------------------------------------------------------
// GEMM type 1: out[n][l][j] = sum_c X[n][c][l] * Wt[j][c] + bias[j]
// Double-buffered smem, FFMA2 inner loop.
// ---------------------------------------------------------------------------
__global__ __launch_bounds__(256) void gemm_xw_kernel(const float* __restrict__ X,
                                                      const float* __restrict__ Wt,
                                                      const float* __restrict__ bias,
                                                      float* __restrict__ out,
                                                      int J) {
    __shared__ float As[2][8][128];
    __shared__ float Bs[2][8][132];

    int n  = blockIdx.z;
    int m0 = blockIdx.y * 128;     // l tile
    int n0 = blockIdx.x * 128;     // j tile
    int tid = threadIdx.x;
    int tx = tid & 15, ty = tid >> 4;

    const float* A = X + n * C * L;

    int akk = tid >> 5;
    int amm = (tid & 31) << 2;
    int bj = tid >> 1;
    int bc = (tid & 1) << 2;
    bool bvalid = (n0 + bj) < J;

    float4 areg = *(const float4*)(A + akk * L + m0 + amm);
    float4 breg = make_float4(0.f, 0.f, 0.f, 0.f);
    if (bvalid) breg = *(const float4*)(Wt + (n0 + bj) * C + bc);

    uint64_t accp[8][4];
#pragma unroll
    for (int i = 0; i < 8; i++)
#pragma unroll
        for (int j = 0; j < 4; j++) accp[i][j] = 0ull;

    *(float4*)&As[0][akk][amm] = areg;
    Bs[0][bc + 0][bj] = breg.x;
    Bs[0][bc + 1][bj] = breg.y;
    Bs[0][bc + 2][bj] = breg.z;
    Bs[0][bc + 3][bj] = breg.w;
    __syncthreads();

    for (int kt = 0; kt < C; kt += 8) {
        int buf = (kt >> 3) & 1;
        bool more = (kt + 8) < C;
        if (more) {
            areg = *(const float4*)(A + (kt + 8 + akk) * L + m0 + amm);
            if (bvalid) breg = *(const float4*)(Wt + (n0 + bj) * C + kt + 8 + bc);
        }
#pragma unroll
        for (int kk = 0; kk < 8; kk++) {
            float a[8];
            *(float4*)(a)     = *(const float4*)&As[buf][kk][ty * 8];
            *(float4*)(a + 4) = *(const float4*)&As[buf][kk][ty * 8 + 4];
            ulonglong2 b01 = *(const ulonglong2*)&Bs[buf][kk][tx * 8];
            ulonglong2 b23 = *(const ulonglong2*)&Bs[buf][kk][tx * 8 + 4];
#pragma unroll
            for (int i = 0; i < 8; i++) {
                uint64_t ap = dup2(a[i]);
                fma2(accp[i][0], ap, b01.x);
                fma2(accp[i][1], ap, b01.y);
                fma2(accp[i][2], ap, b23.x);
                fma2(accp[i][3], ap, b23.y);
            }
        }
        if (more) {
            int nb = buf ^ 1;
            *(float4*)&As[nb][akk][amm] = areg;
            Bs[nb][bc + 0][bj] = breg.x;
            Bs[nb][bc + 1][bj] = breg.y;
            Bs[nb][bc + 2][bj] = breg.z;
            Bs[nb][bc + 3][bj] = breg.w;
            __syncthreads();
        }
    }

    int jb = n0 + tx * 8;
    if (jb < J) {
        float4 bb0 = *(const float4*)(bias + jb);
        float4 bb1 = *(const float4*)(bias + jb + 4);
        float* outp = out + n * L * J;
#pragma unroll
        for (int i = 0; i < 8; i++) {
            int row = m0 + ty * 8 + i;
            float* o = outp + row * J + jb;
            float2 p0 = unpack2(accp[i][0]);
            float2 p1 = unpack2(accp[i][1]);
            float2 p2 = unpack2(accp[i][2]);
            float2 p3 = unpack2(accp[i][3]);
            *(float4*)o       = make_float4(p0.x + bb0.x, p0.y + bb0.y,
                                            p1.x + bb0.z, p1.y + bb0.w);
            *(float4*)(o + 4) = make_float4(p2.x + bb1.x, p2.y + bb1.y,
                                            p3.x + bb1.z, p3.y + bb1.w);
        }
    }
}

// ---------------------------------------------------------------------------
// GEMM type 2 (output projection, writes NCHW directly):
// out[n][m][l] = sum_c Wm[m][c] * S[n][l][c]
// ---------------------------------------------------------------------------
__global__ __launch_bounds__(256) void gemm_out_kernel(const float* __restrict__ Wm,
                                                       const float* __restrict__ S,
                                                       float* __restrict__ out) {
    __shared__ float As[2][8][132];
    __shared__ float Bs[2][8][132];

    int n  = blockIdx.z;
    int m0 = blockIdx.y * 128;   // cout tile
    int n0 = blockIdx.x * 128;   // l tile
    int tid = threadIdx.x;
    int tx = tid & 15, ty = tid >> 4;

    const float* Sb = S + n * L * C;

    int rr = tid >> 1;
    int cc = (tid & 1) << 2;

    float4 areg = *(const float4*)(Wm + (m0 + rr) * C + cc);
    float4 breg = *(const float4*)(Sb + (n0 + rr) * C + cc);

    uint64_t accp[8][4];
#pragma unroll
    for (int i = 0; i < 8; i++)
#pragma unroll
        for (int j = 0; j < 4; j++) accp[i][j] = 0ull;

    As[0][cc + 0][rr] = areg.x;
    As[0][cc + 1][rr] = areg.y;
    As[0][cc + 2][rr] = areg.z;
    As[0][cc + 3][rr] = areg.w;
    Bs[0][cc + 0][rr] = breg.x;
    Bs[0][cc + 1][rr] = breg.y;
    Bs[0][cc + 2][rr] = breg.z;
    Bs[0][cc + 3][rr] = breg.w;
    __syncthreads();

    for (int kt = 0; kt < C; kt += 8) {
        int buf = (kt >> 3) & 1;
        bool more = (kt + 8) < C;
        if (more) {
            areg = *(const float4*)(Wm + (m0 + rr) * C + kt + 8 + cc);
            breg = *(const float4*)(Sb + (n0 + rr) * C + kt + 8 + cc);
        }
#pragma unroll
        for (int kk = 0; kk < 8; kk++) {
            float a[8];
            *(float4*)(a)     = *(const float4*)&As[buf][kk][ty * 8];
            *(float4*)(a + 4) = *(const float4*)&As[buf][kk][ty * 8 + 4];
            ulonglong2 b01 = *(const ulonglong2*)&Bs[buf][kk][tx * 8];
            ulonglong2 b23 = *(const ulonglong2*)&Bs[buf][kk][tx * 8 + 4];
#pragma unroll
            for (int i = 0; i < 8; i++) {
                uint64_t ap = dup2(a[i]);
                fma2(accp[i][0], ap, b01.x);
                fma2(accp[i][1], ap, b01.y);
                fma2(accp[i][2], ap, b23.x);
                fma2(accp[i][3], ap, b23.y);
            }
        }
        if (more) {
            int nb = buf ^ 1;
            As[nb][cc + 0][rr] = areg.x;
            As[nb][cc + 1][rr] = areg.y;
            As[nb][cc + 2][rr] = areg.z;
            As[nb][cc + 3][rr] = areg.w;
            Bs[nb][cc + 0][rr] = breg.x;
            Bs[nb][cc + 1][rr] = breg.y;
            Bs[nb][cc + 2][rr] = breg.z;
            Bs[nb][cc + 3][rr] = breg.w;
            __syncthreads();
        }
    }

#pragma unroll
    for (int i = 0; i < 8; i++) {
        float* o = out + (n * C + m0 + ty * 8 + i) * L + n0 + tx * 8;
        float2 p0 = unpack2(accp[i][0]);
        float2 p1 = unpack2(accp[i][1]);
        float2 p2 = unpack2(accp[i][2]);
        float2 p3 = unpack2(accp[i][3]);
        *(float4*)o       = make_float4(p0.x, p0.y, p1.x, p1.y);
        *(float4*)(o + 4) = make_float4(p2.x, p2.y, p3.x, p3.y);
    }
}

// ---------------------------------------------------------------------------
// Deformable bilinear sampling, v3 (FFMA2 accumulation).
// ---------------------------------------------------------------------------
__global__ __launch_bounds__(256) void sample_kernel() {
    __shared__ float om_s[32][28];   // 27 coeffs + pad

    int tid = threadIdx.x;
    int c4 = tid & 7;
    int li = tid >> 3;
    int l0 = blockIdx.x * 32;
    int g  = blockIdx.y;
    int n  = blockIdx.z;

    for (int i = tid; i < 32 * 27; i += 256) {
        int li2 = i / 27, j = i - li2 * 27;
        om_s[li2][j] = g_om[(n * L + l0 + li2) * JOM + g * 27 + j];
    }
    __syncthreads();

    int l = l0 + li;
    int yy = l >> 6, xx = l & 63;

    const ulonglong2* __restrict__ vp =
        (const ulonglong2*)(g_value + n * L * C + g * CG) + c4;
    const float fyy = (float)yy, fxx = (float)xx;

    uint64_t acc0 = 0ull, acc1 = 0ull;

#pragma unroll
    for (int k = 0; k < KPT; k++) {
        float oy = om_s[li][2 * k];
        float ox = om_s[li][2 * k + 1];
        float mw = om_s[li][18 + k];

        float py = fyy + (float)(k / 3 - 1) + oy;
        float px = fxx + (float)(k % 3 - 1) + ox;
        float y0f = floorf(py), x0f = floorf(px);
        float tyf = py - y0f, txf = px - x0f;
        int y0 = (int)y0f, x0 = (int)x0f;
        int y1 = y0 + 1, x1 = x0 + 1;

        float vy0 = (y0 >= 0 && y0 < H) ? 1.f : 0.f;
        float vy1 = (y1 >= 0 && y1 < H) ? 1.f : 0.f;
        float vx0 = (x0 >= 0 && x0 < W) ? 1.f : 0.f;
        float vx1 = (x1 >= 0 && x1 < W) ? 1.f : 0.f;

        float w00 = mw * (1.f - tyf) * (1.f - txf) * vy0 * vx0;
        float w01 = mw * (1.f - tyf) * txf * vy0 * vx1;
        float w10 = mw * tyf * (1.f - txf) * vy1 * vx0;
        float w11 = mw * tyf * txf * vy1 * vx1;

        int y0c = min(max(y0, 0), H - 1);
        int y1c = min(max(y1, 0), H - 1);
        int x0c = min(max(x0, 0), W - 1);
        int x1c = min(max(x1, 0), W - 1);

        // ulonglong2-unit row offsets: (y*64+x) * (C/4) = (y<<12) + (x<<6)
        int yA = y0c << 12, yB = y1c << 12;
        int xA = x0c << 6,  xB = x1c << 6;

        ulonglong2 v00 = __ldg(vp + (yA + xA));
        ulonglong2 v01 = __ldg(vp + (yA + xB));
        ulonglong2 v10 = __ldg(vp + (yB + xA));
        ulonglong2 v11 = __ldg(vp + (yB + xB));

        uint64_t w00p = dup2(w00), w01p = dup2(w01);
        uint64_t w10p = dup2(w10), w11p = dup2(w11);

        fma2(acc0, w00p, v00.x);
        fma2(acc1, w00p, v00.y);
        fma2(acc0, w01p, v01.x);
        fma2(acc1, w01p, v01.y);
        fma2(acc0, w10p, v10.x);
        fma2(acc1, w10p, v10.y);
        fma2(acc0, w11p, v11.x);
        fma2(acc1, w11p, v11.y);
    }

    ulonglong2 res;
    res.x = acc0;
    res.y = acc1;
    *((ulonglong2*)(g_sampled + (n * L + l) * C + g * CG) + c4) = res;
}

// ---------------------------------------------------------------------------
// Launch: dwconv -> om GEMM -> value GEMM -> sampler -> output GEMM
// ---------------------------------------------------------------------------
extern "C" void kernel_launch(void* const* d_in, const int* in_sizes, int n_in,
                              void* d_out, int out_size) {
    const float* x    = (const float*)d_in[0];
    const float* dw_w = (const float*)d_in[1];
    const float* dw_b = (const float*)d_in[2];
    const float* om_w = (const float*)d_in[3];
    const float* om_b = (const float*)d_in[4];
    const float* vp_w = (const float*)d_in[5];
    const float* vp_b = (const float*)d_in[6];
    const float* op_w = (const float*)d_in[7];
    float* out = (float*)d_out;

    float *p_om_in, *p_value, *p_om, *p_sampled;
    cudaGetSymbolAddress((void**)&p_om_in, g_om_in);
    cudaGetSymbolAddress((void**)&p_value, g_value);
    cudaGetSymbolAddress((void**)&p_om, g_om);
    cudaGetSymbolAddress((void**)&p_sampled, g_sampled);

    dwconv_kernel<<<dim3(L / 256, C, NB), 256>>>(x, dw_w, dw_b);
    gemm_xw_kernel<<<dim3(2, L / 128, NB), 256>>>(p_om_in, om_w, om_b, p_om, JOM);
    gemm_xw_kernel<<<dim3(2, L / 128, NB), 256>>>(x, vp_w, vp_b, p_value, C);
    sample_kernel<<<dim3(L / 32, G, NB), 256>>>();
    gemm_out_kernel<<<dim3(L / 128, 2, NB), 256>>>(op_w, p_sampled, out);
}

// round 7
// speedup vs baseline: 1.3983x; 1.1881x over previous
#include <cuda_runtime.h>
#include <cuda_bf16.h>
#include <cstdint>

// Problem constants
#define NB  8
#define C   256
#define G   8
#define KPT 9
#define H   64
#define W   64
#define L   (H * W)          // 4096
#define CG  (C / G)          // 32
#define KSP 768              // split-K: [hi | lo | hi] * [hi | hi | lo]

// Scratch (static device memory)
__device__ float g_om_in[(size_t)NB * C * L];               // dwconv out (n,c,l) f32
__device__ float g_value[(size_t)NB * L * C];               // value proj (n,l,256) f32
__device__ float g_om_p[(size_t)NB * L * C];                // om padded (n,l,256) f32
__device__ __nv_bfloat16 g_aval[(size_t)NB * L * KSP];      // A' for value GEMM
__device__ __nv_bfloat16 g_aom[(size_t)NB * L * KSP];       // A' for om GEMM
__device__ __nv_bfloat16 g_aop[(size_t)NB * L * KSP];       // A' for out GEMM
__device__ __nv_bfloat16 g_bw[3 * 256 * KSP];               // B' weights (om, vp, op)
__device__ float g_bias_om[256];                            // padded om bias

// ---------------- small helpers ----------------
__device__ __forceinline__ uint32_t smem_u32(const void* p) {
    uint32_t a;
    asm("{ .reg .u64 t; cvta.to.shared.u64 t, %1; cvt.u32.u64 %0, t; }" : "=r"(a) : "l"(p));
    return a;
}
__device__ __forceinline__ void fma2(uint64_t& d, uint64_t a, uint64_t b) {
    asm("fma.rn.f32x2 %0, %1, %2, %0;" : "+l"(d) : "l"(a), "l"(b));
}
__device__ __forceinline__ uint64_t dup2(float a) {
    uint64_t r;
    asm("mov.b64 %0, {%1, %1};" : "=l"(r) : "f"(a));
    return r;
}
__device__ __forceinline__ float2 unpack2(uint64_t v) {
    float2 r;
    asm("mov.b64 {%0, %1}, %2;" : "=f"(r.x), "=f"(r.y) : "l"(v));
    return r;
}
__device__ __forceinline__ uint32_t packbf(__nv_bfloat16 lo, __nv_bfloat16 hi) {
    __nv_bfloat162 t;
    t.x = lo; t.y = hi;
    return *(uint32_t*)&t;
}
__device__ __forceinline__ void bsplit(float v, __nv_bfloat16& h, __nv_bfloat16& l) {
    h = __float2bfloat16(v);
    l = __float2bfloat16(v - __bfloat162float(h));
}

// ---- warp mma primitives (sm_80-compatible; legal under compute_103) ------
__device__ __forceinline__ void ldmatrix_x4(uint32_t& r0, uint32_t& r1,
                                            uint32_t& r2, uint32_t& r3,
                                            uint32_t addr) {
    asm volatile("ldmatrix.sync.aligned.m8n8.x4.shared.b16 {%0,%1,%2,%3}, [%4];"
                 : "=r"(r0), "=r"(r1), "=r"(r2), "=r"(r3) : "r"(addr));
}
__device__ __forceinline__ void ldmatrix_x2(uint32_t& r0, uint32_t& r1,
                                            uint32_t addr) {
    asm volatile("ldmatrix.sync.aligned.m8n8.x2.shared.b16 {%0,%1}, [%2];"
                 : "=r"(r0), "=r"(r1) : "r"(addr));
}
__device__ __forceinline__ void mma16816(float* d, const uint32_t* a,
                                         const uint32_t* b) {
    asm volatile(
        "mma.sync.aligned.m16n8k16.row.col.f32.bf16.bf16.f32 "
        "{%0,%1,%2,%3}, {%4,%5,%6,%7}, {%8,%9}, {%0,%1,%2,%3};"
        : "+f"(d[0]), "+f"(d[1]), "+f"(d[2]), "+f"(d[3])
        : "r"(a[0]), "r"(a[1]), "r"(a[2]), "r"(a[3]), "r"(b[0]), "r"(b[1]));
}

// ---------------------------------------------------------------------------
// Depthwise 3x3 conv, SAME padding
// ---------------------------------------------------------------------------
__global__ __launch_bounds__(256) void dwconv_kernel(const float* __restrict__ x,
                                                     const float* __restrict__ w,
                                                     const float* __restrict__ b) {
    int l = blockIdx.x * 256 + threadIdx.x;
    int c = blockIdx.y;
    int n = blockIdx.z;
    int yy = l >> 6, xx = l & 63;
    const float* xp = x + (n * C + c) * L;
    const float* wp = w + c * 9;
    float acc = b[c];
#pragma unroll
    for (int dy = -1; dy <= 1; dy++) {
#pragma unroll
        for (int dx = -1; dx <= 1; dx++) {
            int y2 = yy + dy, x2 = xx + dx;
            if (y2 >= 0 && y2 < H && x2 >= 0 && x2 < W)
                acc += wp[(dy + 1) * 3 + (dx + 1)] * xp[y2 * W + x2];
        }
    }
    g_om_in[(n * C + c) * L + l] = acc;
}

// ---------------------------------------------------------------------------
// Weight prep: Wsrc (J,256) f32 -> B' (256 rows, 768) bf16 [hi | hi | lo]
// ---------------------------------------------------------------------------
__global__ __launch_bounds__(256) void prep_w_kernel(const float* __restrict__ om_w,
                                                     const float* __restrict__ om_b,
                                                     const float* __restrict__ vp_w,
                                                     const float* __restrict__ op_w) {
    int j = blockIdx.x;
    int ws = blockIdx.y;
    int c = threadIdx.x;
    const float* Wsrc = (ws == 0) ? om_w : (ws == 1) ? vp_w : op_w;
    int Jrows = (ws == 0) ? 216 : 256;
    float v = (j < Jrows) ? Wsrc[j * 256 + c] : 0.f;
    __nv_bfloat16 h, lo;
    bsplit(v, h, lo);
    __nv_bfloat16* outw = g_bw + ((size_t)ws * 256 + j) * KSP;
    outw[c] = h;
    outw[256 + c] = h;
    outw[512 + c] = lo;
    if (ws == 0 && j == 0)
        g_bias_om[c] = (c < 216) ? om_b[c] : 0.f;
}

// ---------------------------------------------------------------------------
// Transpose-convert: X (n, 256, L) f32 -> A' (n, L, 768) bf16 [hi | lo | hi]
// ---------------------------------------------------------------------------
__global__ __launch_bounds__(256) void convT_kernel(const float* __restrict__ X,
                                                    __nv_bfloat16* __restrict__ Ab) {
    int l = blockIdx.x * 256 + threadIdx.x;
    int n = blockIdx.y;
    const float* xp = X + ((size_t)n * 256) * L + l;
    char* ob = (char*)(Ab + ((size_t)(n * L + l)) * KSP);
#pragma unroll 4
    for (int c8 = 0; c8 < 32; c8++) {
        uint32_t hi[4], lw[4];
#pragma unroll
        for (int j = 0; j < 4; j++) {
            float a = xp[(size_t)(c8 * 8 + 2 * j) * L];
            float b = xp[(size_t)(c8 * 8 + 2 * j + 1) * L];
            __nv_bfloat16 ha, la, hb, lb;
            bsplit(a, ha, la);
            bsplit(b, hb, lb);
            hi[j] = packbf(ha, hb);
            lw[j] = packbf(la, lb);
        }
        uint4 hv = make_uint4(hi[0], hi[1], hi[2], hi[3]);
        uint4 lv = make_uint4(lw[0], lw[1], lw[2], lw[3]);
        *(uint4*)(ob + c8 * 16) = hv;            // hi   @ elems [0,256)
        *(uint4*)(ob + 512 + c8 * 16) = lv;      // lo   @ elems [256,512)
        *(uint4*)(ob + 1024 + c8 * 16) = hv;     // hi   @ elems [512,768)
    }
}

// ---------------------------------------------------------------------------
// Warp-mma bf16 GEMM: D(n)[m0..m0+128, n0..n0+128) = A'(n) x B'^T  (K=768)
// CTA 128x128, 8 warps (2m x 4n), each warp 64x32 via m16n8k16 mma.
// mode 0: out row-major (n, L, 256) f32 + bias
// mode 1: out NCHW (n, 256, L) f32, no bias
// ---------------------------------------------------------------------------
#define BK 32
#define ASTR 40              // padded smem row stride (bf16 units)

__global__ __launch_bounds__(256)
void gemm_mma_kernel(const __nv_bfloat16* __restrict__ Ab,
                     const __nv_bfloat16* __restrict__ Bb,
                     const float* __restrict__ bias,
                     float* __restrict__ outp,
                     int mode) {
    __shared__ __nv_bfloat16 As[2][128][ASTR];
    __shared__ __nv_bfloat16 Bs[2][128][ASTR];

    int tid = threadIdx.x;
    int lane = tid & 31;
    int wid = tid >> 5;
    int warp_m = wid >> 2;       // 0..1
    int warp_n = wid & 3;        // 0..3
    int n0 = blockIdx.x * 128;
    int m0 = blockIdx.y * 128;
    int n  = blockIdx.z;

    const __nv_bfloat16* Ag = Ab + ((size_t)(n * L + m0)) * KSP;
    const __nv_bfloat16* Bg = Bb + (size_t)n0 * KSP;

    int lrow = tid >> 1;             // 0..127
    int lcol = (tid & 1) << 4;       // 0 or 16 (bf16 units)

    // ldmatrix source addresses (smem, byte offsets added per-tile)
    uint32_t a_s0 = smem_u32(&As[0][0][0]);
    uint32_t b_s0 = smem_u32(&Bs[0][0][0]);
    const uint32_t BUFB = 128 * ASTR * 2;   // bytes per buffer

    int a_r = warp_m * 64 + (lane & 15);
    int a_k = (lane >> 4) << 3;
    int b_r = warp_n * 32 + (lane & 7);
    int b_k = ((lane >> 3) & 1) << 3;

    float d[4][4][4];
#pragma unroll
    for (int i = 0; i < 4; i++)
#pragma unroll
        for (int j = 0; j < 4; j++)
#pragma unroll
            for (int k = 0; k < 4; k++) d[i][j][k] = 0.f;

    // prologue: chunk 0 -> buf 0
    {
        const uint4* ga = (const uint4*)(Ag + (size_t)lrow * KSP + lcol);
        const uint4* gb = (const uint4*)(Bg + (size_t)lrow * KSP + lcol);
        uint4* sa = (uint4*)&As[0][lrow][lcol];
        uint4* sb = (uint4*)&Bs[0][lrow][lcol];
        sa[0] = ga[0];
        sa[1] = ga[1];
        sb[0] = gb[0];
        sb[1] = gb[1];
    }
    __syncthreads();

    const int NKC = KSP / BK;    // 24
    uint4 pa0, pa1, pb0, pb1;

    for (int kc = 0; kc < NKC; kc++) {
        int buf = kc & 1;
        if (kc + 1 < NKC) {
            const uint4* ga = (const uint4*)(Ag + (size_t)lrow * KSP + (kc + 1) * BK + lcol);
            const uint4* gb = (const uint4*)(Bg + (size_t)lrow * KSP + (kc + 1) * BK + lcol);
            pa0 = ga[0]; pa1 = ga[1];
            pb0 = gb[0]; pb1 = gb[1];
        }

#pragma unroll
        for (int kk = 0; kk < 2; kk++) {
            uint32_t b[4][2];
#pragma unroll
            for (int nt = 0; nt < 4; nt++) {
                uint32_t addr = b_s0 + buf * BUFB +
                    (((b_r + nt * 8) * ASTR) + kk * 16 + b_k) * 2;
                ldmatrix_x2(b[nt][0], b[nt][1], addr);
            }
#pragma unroll
            for (int mt = 0; mt < 4; mt++) {
                uint32_t a[4];
                uint32_t addr = a_s0 + buf * BUFB +
                    (((a_r + mt * 16) * ASTR) + kk * 16 + a_k) * 2;
                ldmatrix_x4(a[0], a[1], a[2], a[3], addr);
#pragma unroll
                for (int nt = 0; nt < 4; nt++)
                    mma16816(d[mt][nt], a, b[nt]);
            }
        }

        if (kc + 1 < NKC) {
            int nb = buf ^ 1;
            uint4* sa = (uint4*)&As[nb][lrow][lcol];
            uint4* sb = (uint4*)&Bs[nb][lrow][lcol];
            sa[0] = pa0; sa[1] = pa1;
            sb[0] = pb0; sb[1] = pb1;
            __syncthreads();
        }
    }

    // epilogue
    int rbase = m0 + warp_m * 64 + (lane >> 2);
    int cbase = n0 + warp_n * 32 + (lane & 3) * 2;
    if (mode == 0) {
        float* ob = outp + (size_t)n * L * 256;
#pragma unroll
        for (int mt = 0; mt < 4; mt++) {
#pragma unroll
            for (int nt = 0; nt < 4; nt++) {
                int r = rbase + mt * 16;
                int c = cbase + nt * 8;
                float bx = __ldg(bias + c), by = __ldg(bias + c + 1);
                *(float2*)(ob + (size_t)r * 256 + c) =
                    make_float2(d[mt][nt][0] + bx, d[mt][nt][1] + by);
                *(float2*)(ob + (size_t)(r + 8) * 256 + c) =
                    make_float2(d[mt][nt][2] + bx, d[mt][nt][3] + by);
            }
        }
    } else {
        float* ob = outp + (size_t)n * 256 * L;
#pragma unroll
        for (int mt = 0; mt < 4; mt++) {
#pragma unroll
            for (int nt = 0; nt < 4; nt++) {
                int r = rbase + mt * 16;
                int c = cbase + nt * 8;
                float* p0 = ob + (size_t)c * L;
                float* p1 = ob + (size_t)(c + 1) * L;
                p0[r] = d[mt][nt][0];
                p1[r] = d[mt][nt][1];
                p0[r + 8] = d[mt][nt][2];
                p1[r + 8] = d[mt][nt][3];
            }
        }
    }
}

// ---------------------------------------------------------------------------
// Deformable bilinear sampling; emits split-bf16 A' for the output GEMM.
// ---------------------------------------------------------------------------
__global__ __launch_bounds__(256) void sample_kernel() {
    __shared__ float om_s[32][28];

    int tid = threadIdx.x;
    int c4 = tid & 7;
    int li = tid >> 3;
    int l0 = blockIdx.x * 32;
    int g  = blockIdx.y;
    int n  = blockIdx.z;

    for (int i = tid; i < 32 * 27; i += 256) {
        int li2 = i / 27, j = i - li2 * 27;
        om_s[li2][j] = g_om_p[(size_t)(n * L + l0 + li2) * 256 + g * 27 + j];
    }
    __syncthreads();

    int l = l0 + li;
    int yy = l >> 6, xx = l & 63;

    const ulonglong2* __restrict__ vp =
        (const ulonglong2*)(g_value + (size_t)n * L * C + g * CG) + c4;
    const float fyy = (float)yy, fxx = (float)xx;

    uint64_t acc0 = 0ull, acc1 = 0ull;

#pragma unroll
    for (int k = 0; k < KPT; k++) {
        float oy = om_s[li][2 * k];
        float ox = om_s[li][2 * k + 1];
        float mw = om_s[li][18 + k];

        float py = fyy + (float)(k / 3 - 1) + oy;
        float px = fxx + (float)(k % 3 - 1) + ox;
        float y0f = floorf(py), x0f = floorf(px);
        float tyf = py - y0f, txf = px - x0f;
        int y0 = (int)y0f, x0 = (int)x0f;
        int y1 = y0 + 1, x1 = x0 + 1;

        float vy0 = (y0 >= 0 && y0 < H) ? 1.f : 0.f;
        float vy1 = (y1 >= 0 && y1 < H) ? 1.f : 0.f;
        float vx0 = (x0 >= 0 && x0 < W) ? 1.f : 0.f;
        float vx1 = (x1 >= 0 && x1 < W) ? 1.f : 0.f;

        float w00 = mw * (1.f - tyf) * (1.f - txf) * vy0 * vx0;
        float w01 = mw * (1.f - tyf) * txf * vy0 * vx1;
        float w10 = mw * tyf * (1.f - txf) * vy1 * vx0;
        float w11 = mw * tyf * txf * vy1 * vx1;

        int y0c = min(max(y0, 0), H - 1);
        int y1c = min(max(y1, 0), H - 1);
        int x0c = min(max(x0, 0), W - 1);
        int x1c = min(max(x1, 0), W - 1);

        int yA = y0c << 12, yB = y1c << 12;
        int xA = x0c << 6,  xB = x1c << 6;

        ulonglong2 v00 = __ldg(vp + (yA + xA));
        ulonglong2 v01 = __ldg(vp + (yA + xB));
        ulonglong2 v10 = __ldg(vp + (yB + xA));
        ulonglong2 v11 = __ldg(vp + (yB + xB));

        uint64_t w00p = dup2(w00), w01p = dup2(w01);
        uint64_t w10p = dup2(w10), w11p = dup2(w11);

        fma2(acc0, w00p, v00.x);
        fma2(acc1, w00p, v00.y);
        fma2(acc0, w01p, v01.x);
        fma2(acc1, w01p, v01.y);
        fma2(acc0, w10p, v10.x);
        fma2(acc1, w10p, v10.y);
        fma2(acc0, w11p, v11.x);
        fma2(acc1, w11p, v11.y);
    }

    float2 a01 = unpack2(acc0);
    float2 a23 = unpack2(acc1);
    __nv_bfloat16 h0, l0b, h1, l1b, h2, l2b, h3, l3b;
    bsplit(a01.x, h0, l0b);
    bsplit(a01.y, h1, l1b);
    bsplit(a23.x, h2, l2b);
    bsplit(a23.y, h3, l3b);
    uint2 hv = make_uint2(packbf(h0, h1), packbf(h2, h3));
    uint2 lv = make_uint2(packbf(l0b, l1b), packbf(l2b, l3b));

    char* ob = (char*)(g_aop + ((size_t)(n * L + l)) * KSP) + (g * 32 + c4 * 4) * 2;
    *(uint2*)(ob) = hv;           // hi  @ elems [0,256)
    *(uint2*)(ob + 512) = lv;     // lo  @ elems [256,512)
    *(uint2*)(ob + 1024) = hv;    // hi  @ elems [512,768)
}

// ---------------------------------------------------------------------------
// Launch
// ---------------------------------------------------------------------------
extern "C" void kernel_launch(void* const* d_in, const int* in_sizes, int n_in,
                              void* d_out, int out_size) {
    const float* x    = (const float*)d_in[0];
    const float* dw_w = (const float*)d_in[1];
    const float* dw_b = (const float*)d_in[2];
    const float* om_w = (const float*)d_in[3];
    const float* om_b = (const float*)d_in[4];
    const float* vp_w = (const float*)d_in[5];
    const float* vp_b = (const float*)d_in[6];
    const float* op_w = (const float*)d_in[7];
    float* out = (float*)d_out;

    float *p_om_in, *p_value, *p_om_p, *p_bias_om;
    __nv_bfloat16 *p_aval, *p_aom, *p_aop, *p_bw;
    cudaGetSymbolAddress((void**)&p_om_in, g_om_in);
    cudaGetSymbolAddress((void**)&p_value, g_value);
    cudaGetSymbolAddress((void**)&p_om_p, g_om_p);
    cudaGetSymbolAddress((void**)&p_bias_om, g_bias_om);
    cudaGetSymbolAddress((void**)&p_aval, g_aval);
    cudaGetSymbolAddress((void**)&p_aom, g_aom);
    cudaGetSymbolAddress((void**)&p_aop, g_aop);
    cudaGetSymbolAddress((void**)&p_bw, g_bw);

    prep_w_kernel<<<dim3(256, 3), 256>>>(om_w, om_b, vp_w, op_w);
    dwconv_kernel<<<dim3(L / 256, C, NB), 256>>>(x, dw_w, dw_b);
    convT_kernel<<<dim3(L / 256, NB), 256>>>(x, p_aval);
    convT_kernel<<<dim3(L / 256, NB), 256>>>(p_om_in, p_aom);
    gemm_mma_kernel<<<dim3(2, 32, NB), 256>>>(p_aom, p_bw, p_bias_om, p_om_p, 0);
    gemm_mma_kernel<<<dim3(2, 32, NB), 256>>>(p_aval, p_bw + (size_t)256 * KSP, vp_b, p_value, 0);
    sample_kernel<<<dim3(L / 32, G, NB), 256>>>();
    gemm_mma_kernel<<<dim3(2, 32, NB), 256>>>(p_aop, p_bw + (size_t)2 * 256 * KSP, p_bias_om, out, 1);
}

// round 8
// speedup vs baseline: 1.4826x; 1.0602x over previous
#include <cuda_runtime.h>
#include <cuda_bf16.h>
#include <cstdint>

// Problem constants
#define NB  8
#define C   256
#define G   8
#define KPT 9
#define H   64
#define W   64
#define L   (H * W)          // 4096
#define CG  (C / G)          // 32
#define KA  512              // stored K: A=[hi|lo], B=[hi|lo]; GEMM runs K=768 via remap

// Scratch (static device memory)
__device__ float g_value[(size_t)NB * L * C];               // value proj (n,l,256) f32
__device__ float g_om_p[(size_t)NB * L * C];                // om padded (n,l,256) f32
__device__ __nv_bfloat16 g_aval[(size_t)NB * L * KA];       // A' for value GEMM
__device__ __nv_bfloat16 g_aom[(size_t)NB * L * KA];        // A' for om GEMM
__device__ __nv_bfloat16 g_aop[(size_t)NB * L * KA];        // A' for out GEMM
__device__ __nv_bfloat16 g_bw[3 * 256 * KA];                // B' weights (om, vp, op)
__device__ float g_bias_om[256];                            // padded om bias

// ---------------- small helpers ----------------
__device__ __forceinline__ uint32_t smem_u32(const void* p) {
    uint32_t a;
    asm("{ .reg .u64 t; cvta.to.shared.u64 t, %1; cvt.u32.u64 %0, t; }" : "=r"(a) : "l"(p));
    return a;
}
__device__ __forceinline__ void fma2(uint64_t& d, uint64_t a, uint64_t b) {
    asm("fma.rn.f32x2 %0, %1, %2, %0;" : "+l"(d) : "l"(a), "l"(b));
}
__device__ __forceinline__ uint64_t dup2(float a) {
    uint64_t r;
    asm("mov.b64 %0, {%1, %1};" : "=l"(r) : "f"(a));
    return r;
}
__device__ __forceinline__ float2 unpack2(uint64_t v) {
    float2 r;
    asm("mov.b64 {%0, %1}, %2;" : "=f"(r.x), "=f"(r.y) : "l"(v));
    return r;
}
__device__ __forceinline__ uint32_t packbf(__nv_bfloat16 lo, __nv_bfloat16 hi) {
    __nv_bfloat162 t;
    t.x = lo; t.y = hi;
    return *(uint32_t*)&t;
}
__device__ __forceinline__ void bsplit(float v, __nv_bfloat16& h, __nv_bfloat16& l) {
    h = __float2bfloat16(v);
    l = __float2bfloat16(v - __bfloat162float(h));
}

// ---- warp mma primitives (sm_80-compatible; legal under compute_103) ------
__device__ __forceinline__ void ldmatrix_x4(uint32_t& r0, uint32_t& r1,
                                            uint32_t& r2, uint32_t& r3,
                                            uint32_t addr) {
    asm volatile("ldmatrix.sync.aligned.m8n8.x4.shared.b16 {%0,%1,%2,%3}, [%4];"
                 : "=r"(r0), "=r"(r1), "=r"(r2), "=r"(r3) : "r"(addr));
}
__device__ __forceinline__ void ldmatrix_x2(uint32_t& r0, uint32_t& r1,
                                            uint32_t addr) {
    asm volatile("ldmatrix.sync.aligned.m8n8.x2.shared.b16 {%0,%1}, [%2];"
                 : "=r"(r0), "=r"(r1) : "r"(addr));
}
__device__ __forceinline__ void mma16816(float* d, const uint32_t* a,
                                         const uint32_t* b) {
    asm volatile(
        "mma.sync.aligned.m16n8k16.row.col.f32.bf16.bf16.f32 "
        "{%0,%1,%2,%3}, {%4,%5,%6,%7}, {%8,%9}, {%0,%1,%2,%3};"
        : "+f"(d[0]), "+f"(d[1]), "+f"(d[2]), "+f"(d[3])
        : "r"(a[0]), "r"(a[1]), "r"(a[2]), "r"(a[3]), "r"(b[0]), "r"(b[1]));
}

// ---------------------------------------------------------------------------
// Weight prep: Wsrc (J,256) f32 -> B' (256 rows, 512) bf16 [hi | lo]
// ---------------------------------------------------------------------------
__global__ __launch_bounds__(256) void prep_w_kernel(const float* __restrict__ om_w,
                                                     const float* __restrict__ om_b,
                                                     const float* __restrict__ vp_w,
                                                     const float* __restrict__ op_w) {
    int j = blockIdx.x;
    int ws = blockIdx.y;
    int c = threadIdx.x;
    const float* Wsrc = (ws == 0) ? om_w : (ws == 1) ? vp_w : op_w;
    int Jrows = (ws == 0) ? 216 : 256;
    float v = (j < Jrows) ? Wsrc[j * 256 + c] : 0.f;
    __nv_bfloat16 h, lo;
    bsplit(v, h, lo);
    __nv_bfloat16* outw = g_bw + ((size_t)ws * 256 + j) * KA;
    outw[c] = h;
    outw[256 + c] = lo;
    if (ws == 0 && j == 0)
        g_bias_om[c] = (c < 216) ? om_b[c] : 0.f;
}

// ---------------------------------------------------------------------------
// Transpose-convert: X (n, 256, L) f32 -> A' (n, L, 512) bf16 [hi | lo]
// grid (L/256, 4, NB); blockIdx.y selects 64-channel slab (occupancy fix).
// ---------------------------------------------------------------------------
__global__ __launch_bounds__(256) void convT_kernel(const float* __restrict__ X,
                                                    __nv_bfloat16* __restrict__ Ab) {
    int l = blockIdx.x * 256 + threadIdx.x;
    int c80 = blockIdx.y * 8;
    int n = blockIdx.z;
    const float* xp = X + ((size_t)n * 256) * L + l;
    char* ob = (char*)(Ab + ((size_t)(n * L + l)) * KA);
#pragma unroll
    for (int c8 = c80; c8 < c80 + 8; c8++) {
        uint32_t hi[4], lw[4];
#pragma unroll
        for (int j = 0; j < 4; j++) {
            float a = xp[(size_t)(c8 * 8 + 2 * j) * L];
            float b = xp[(size_t)(c8 * 8 + 2 * j + 1) * L];
            __nv_bfloat16 ha, la, hb, lb;
            bsplit(a, ha, la);
            bsplit(b, hb, lb);
            hi[j] = packbf(ha, hb);
            lw[j] = packbf(la, lb);
        }
        *(uint4*)(ob + c8 * 16)       = make_uint4(hi[0], hi[1], hi[2], hi[3]);
        *(uint4*)(ob + 512 + c8 * 16) = make_uint4(lw[0], lw[1], lw[2], lw[3]);
    }
}

// ---------------------------------------------------------------------------
// Fused depthwise-conv + transpose-convert for the om path:
// A'om (n, L, 512) bf16 [hi | lo] where value = dwconv3x3(x)[c][l] + dw_b[c]
// grid (L/256, 4, NB)
// ---------------------------------------------------------------------------
__global__ __launch_bounds__(256) void convT_om_kernel(const float* __restrict__ x,
                                                       const float* __restrict__ dw,
                                                       const float* __restrict__ db,
                                                       __nv_bfloat16* __restrict__ Ab) {
    int l = blockIdx.x * 256 + threadIdx.x;
    int c80 = blockIdx.y * 8;
    int n = blockIdx.z;
    int yy = l >> 6, xx = l & 63;

    // precompute 9 neighbor offsets + validity (shared across channels)
    int offs[9];
    float val9[9];
#pragma unroll
    for (int t = 0; t < 9; t++) {
        int dy = t / 3 - 1, dx = t % 3 - 1;
        int y2 = yy + dy, x2 = xx + dx;
        bool v = (y2 >= 0 && y2 < H && x2 >= 0 && x2 < W);
        offs[t] = v ? (y2 * W + x2) : 0;
        val9[t] = v ? 1.f : 0.f;
    }

    const float* xb = x + ((size_t)n * 256) * L;
    char* ob = (char*)(Ab + ((size_t)(n * L + l)) * KA);

#pragma unroll
    for (int c8 = c80; c8 < c80 + 8; c8++) {
        uint32_t hi[4], lw[4];
#pragma unroll
        for (int j = 0; j < 4; j++) {
            float r[2];
#pragma unroll
            for (int s = 0; s < 2; s++) {
                int c = c8 * 8 + 2 * j + s;
                const float* xc = xb + (size_t)c * L;
                const float* wc = dw + c * 9;
                float acc = db[c];
#pragma unroll
                for (int t = 0; t < 9; t++)
                    acc += wc[t] * val9[t] * xc[offs[t]];
                r[s] = acc;
            }
            __nv_bfloat16 ha, la, hb, lb;
            bsplit(r[0], ha, la);
            bsplit(r[1], hb, lb);
            hi[j] = packbf(ha, hb);
            lw[j] = packbf(la, lb);
        }
        *(uint4*)(ob + c8 * 16)       = make_uint4(hi[0], hi[1], hi[2], hi[3]);
        *(uint4*)(ob + 512 + c8 * 16) = make_uint4(lw[0], lw[1], lw[2], lw[3]);
    }
}

// ---------------------------------------------------------------------------
// Warp-mma bf16 GEMM with split remap. Storage K=512 both sides; logical
// K=768: kc<8: ah*bh | 8..15: al*bh | 16..23: ah*bl.
// CTA 128x128, 8 warps (2m x 4n), m16n8k16.
// mode 0: out row-major (n, L, 256) f32 + bias;  mode 1: NCHW, no bias.
// ---------------------------------------------------------------------------
#define BK 32
#define ASTR 40              // padded smem row stride (bf16 units)
#define NKC 24

__device__ __forceinline__ int a_seg(int kc) {
    return (kc < 8) ? kc * BK : (kc < 16) ? 256 + (kc - 8) * BK : (kc - 16) * BK;
}
__device__ __forceinline__ int b_seg(int kc) {
    return (kc < 16) ? (kc & 7) * BK : 256 + (kc - 16) * BK;
}

__global__ __launch_bounds__(256)
void gemm_mma_kernel(const __nv_bfloat16* __restrict__ Ab,
                     const __nv_bfloat16* __restrict__ Bb,
                     const float* __restrict__ bias,
                     float* __restrict__ outp,
                     int mode) {
    __shared__ __nv_bfloat16 As[2][128][ASTR];
    __shared__ __nv_bfloat16 Bs[2][128][ASTR];

    int tid = threadIdx.x;
    int lane = tid & 31;
    int wid = tid >> 5;
    int warp_m = wid >> 2;       // 0..1
    int warp_n = wid & 3;        // 0..3
    int n0 = blockIdx.x * 128;
    int m0 = blockIdx.y * 128;
    int n  = blockIdx.z;

    const __nv_bfloat16* Ag = Ab + ((size_t)(n * L + m0)) * KA;
    const __nv_bfloat16* Bg = Bb + (size_t)n0 * KA;

    int lrow = tid >> 1;             // 0..127
    int lcol = (tid & 1) << 4;       // 0 or 16 (bf16 units)

    uint32_t a_s0 = smem_u32(&As[0][0][0]);
    uint32_t b_s0 = smem_u32(&Bs[0][0][0]);
    const uint32_t BUFB = 128 * ASTR * 2;   // bytes per buffer

    int a_r = warp_m * 64 + (lane & 15);
    int a_k = (lane >> 4) << 3;
    int b_r = warp_n * 32 + (lane & 7);
    int b_k = ((lane >> 3) & 1) << 3;

    float d[4][4][4];
#pragma unroll
    for (int i = 0; i < 4; i++)
#pragma unroll
        for (int j = 0; j < 4; j++)
#pragma unroll
            for (int k = 0; k < 4; k++) d[i][j][k] = 0.f;

    // prologue: chunk 0 -> buf 0 (aseg=0, bseg=0)
    {
        const uint4* ga = (const uint4*)(Ag + (size_t)lrow * KA + lcol);
        const uint4* gb = (const uint4*)(Bg + (size_t)lrow * KA + lcol);
        uint4* sa = (uint4*)&As[0][lrow][lcol];
        uint4* sb = (uint4*)&Bs[0][lrow][lcol];
        sa[0] = ga[0];
        sa[1] = ga[1];
        sb[0] = gb[0];
        sb[1] = gb[1];
    }
    __syncthreads();

    uint4 pa0, pa1, pb0, pb1;

    for (int kc = 0; kc < NKC; kc++) {
        int buf = kc & 1;
        if (kc + 1 < NKC) {
            int ao = a_seg(kc + 1);
            int bo = b_seg(kc + 1);
            const uint4* ga = (const uint4*)(Ag + (size_t)lrow * KA + ao + lcol);
            const uint4* gb = (const uint4*)(Bg + (size_t)lrow * KA + bo + lcol);
            pa0 = ga[0]; pa1 = ga[1];
            pb0 = gb[0]; pb1 = gb[1];
        }

#pragma unroll
        for (int kk = 0; kk < 2; kk++) {
            uint32_t b[4][2];
#pragma unroll
            for (int nt = 0; nt < 4; nt++) {
                uint32_t addr = b_s0 + buf * BUFB +
                    (((b_r + nt * 8) * ASTR) + kk * 16 + b_k) * 2;
                ldmatrix_x2(b[nt][0], b[nt][1], addr);
            }
#pragma unroll
            for (int mt = 0; mt < 4; mt++) {
                uint32_t a[4];
                uint32_t addr = a_s0 + buf * BUFB +
                    (((a_r + mt * 16) * ASTR) + kk * 16 + a_k) * 2;
                ldmatrix_x4(a[0], a[1], a[2], a[3], addr);
#pragma unroll
                for (int nt = 0; nt < 4; nt++)
                    mma16816(d[mt][nt], a, b[nt]);
            }
        }

        if (kc + 1 < NKC) {
            int nb = buf ^ 1;
            uint4* sa = (uint4*)&As[nb][lrow][lcol];
            uint4* sb = (uint4*)&Bs[nb][lrow][lcol];
            sa[0] = pa0; sa[1] = pa1;
            sb[0] = pb0; sb[1] = pb1;
            __syncthreads();
        }
    }

    // epilogue
    int rbase = m0 + warp_m * 64 + (lane >> 2);
    int cbase = n0 + warp_n * 32 + (lane & 3) * 2;
    if (mode == 0) {
        float* ob = outp + (size_t)n * L * 256;
#pragma unroll
        for (int mt = 0; mt < 4; mt++) {
#pragma unroll
            for (int nt = 0; nt < 4; nt++) {
                int r = rbase + mt * 16;
                int c = cbase + nt * 8;
                float bx = __ldg(bias + c), by = __ldg(bias + c + 1);
                *(float2*)(ob + (size_t)r * 256 + c) =
                    make_float2(d[mt][nt][0] + bx, d[mt][nt][1] + by);
                *(float2*)(ob + (size_t)(r + 8) * 256 + c) =
                    make_float2(d[mt][nt][2] + bx, d[mt][nt][3] + by);
            }
        }
    } else {
        float* ob = outp + (size_t)n * 256 * L;
#pragma unroll
        for (int mt = 0; mt < 4; mt++) {
#pragma unroll
            for (int nt = 0; nt < 4; nt++) {
                int r = rbase + mt * 16;
                int c = cbase + nt * 8;
                float* p0 = ob + (size_t)c * L;
                float* p1 = ob + (size_t)(c + 1) * L;
                p0[r] = d[mt][nt][0];
                p1[r] = d[mt][nt][1];
                p0[r + 8] = d[mt][nt][2];
                p1[r + 8] = d[mt][nt][3];
            }
        }
    }
}

// ---------------------------------------------------------------------------
// Deformable bilinear sampling; emits split-bf16 A' [hi | lo] for out GEMM.
// ---------------------------------------------------------------------------
__global__ __launch_bounds__(256) void sample_kernel() {
    __shared__ float om_s[32][28];

    int tid = threadIdx.x;
    int c4 = tid & 7;
    int li = tid >> 3;
    int l0 = blockIdx.x * 32;
    int g  = blockIdx.y;
    int n  = blockIdx.z;

    for (int i = tid; i < 32 * 27; i += 256) {
        int li2 = i / 27, j = i - li2 * 27;
        om_s[li2][j] = g_om_p[(size_t)(n * L + l0 + li2) * 256 + g * 27 + j];
    }
    __syncthreads();

    int l = l0 + li;
    int yy = l >> 6, xx = l & 63;

    const ulonglong2* __restrict__ vp =
        (const ulonglong2*)(g_value + (size_t)n * L * C + g * CG) + c4;
    const float fyy = (float)yy, fxx = (float)xx;

    uint64_t acc0 = 0ull, acc1 = 0ull;

#pragma unroll
    for (int k = 0; k < KPT; k++) {
        float oy = om_s[li][2 * k];
        float ox = om_s[li][2 * k + 1];
        float mw = om_s[li][18 + k];

        float py = fyy + (float)(k / 3 - 1) + oy;
        float px = fxx + (float)(k % 3 - 1) + ox;
        float y0f = floorf(py), x0f = floorf(px);
        float tyf = py - y0f, txf = px - x0f;
        int y0 = (int)y0f, x0 = (int)x0f;
        int y1 = y0 + 1, x1 = x0 + 1;

        float vy0 = (y0 >= 0 && y0 < H) ? 1.f : 0.f;
        float vy1 = (y1 >= 0 && y1 < H) ? 1.f : 0.f;
        float vx0 = (x0 >= 0 && x0 < W) ? 1.f : 0.f;
        float vx1 = (x1 >= 0 && x1 < W) ? 1.f : 0.f;

        float w00 = mw * (1.f - tyf) * (1.f - txf) * vy0 * vx0;
        float w01 = mw * (1.f - tyf) * txf * vy0 * vx1;
        float w10 = mw * tyf * (1.f - txf) * vy1 * vx0;
        float w11 = mw * tyf * txf * vy1 * vx1;

        int y0c = min(max(y0, 0), H - 1);
        int y1c = min(max(y1, 0), H - 1);
        int x0c = min(max(x0, 0), W - 1);
        int x1c = min(max(x1, 0), W - 1);

        int yA = y0c << 12, yB = y1c << 12;
        int xA = x0c << 6,  xB = x1c << 6;

        ulonglong2 v00 = __ldg(vp + (yA + xA));
        ulonglong2 v01 = __ldg(vp + (yA + xB));
        ulonglong2 v10 = __ldg(vp + (yB + xA));
        ulonglong2 v11 = __ldg(vp + (yB + xB));

        uint64_t w00p = dup2(w00), w01p = dup2(w01);
        uint64_t w10p = dup2(w10), w11p = dup2(w11);

        fma2(acc0, w00p, v00.x);
        fma2(acc1, w00p, v00.y);
        fma2(acc0, w01p, v01.x);
        fma2(acc1, w01p, v01.y);
        fma2(acc0, w10p, v10.x);
        fma2(acc1, w10p, v10.y);
        fma2(acc0, w11p, v11.x);
        fma2(acc1, w11p, v11.y);
    }

    float2 a01 = unpack2(acc0);
    float2 a23 = unpack2(acc1);
    __nv_bfloat16 h0, l0b, h1, l1b, h2, l2b, h3, l3b;
    bsplit(a01.x, h0, l0b);
    bsplit(a01.y, h1, l1b);
    bsplit(a23.x, h2, l2b);
    bsplit(a23.y, h3, l3b);
    uint2 hv = make_uint2(packbf(h0, h1), packbf(h2, h3));
    uint2 lv = make_uint2(packbf(l0b, l1b), packbf(l2b, l3b));

    char* ob = (char*)(g_aop + ((size_t)(n * L + l)) * KA) + (g * 32 + c4 * 4) * 2;
    *(uint2*)(ob)       = hv;     // hi @ elems [0,256)
    *(uint2*)(ob + 512) = lv;     // lo @ elems [256,512)
}

// ---------------------------------------------------------------------------
// Launch
// ---------------------------------------------------------------------------
extern "C" void kernel_launch(void* const* d_in, const int* in_sizes, int n_in,
                              void* d_out, int out_size) {
    const float* x    = (const float*)d_in[0];
    const float* dw_w = (const float*)d_in[1];
    const float* dw_b = (const float*)d_in[2];
    const float* om_w = (const float*)d_in[3];
    const float* om_b = (const float*)d_in[4];
    const float* vp_w = (const float*)d_in[5];
    const float* vp_b = (const float*)d_in[6];
    const float* op_w = (const float*)d_in[7];
    float* out = (float*)d_out;

    float *p_value, *p_om_p, *p_bias_om;
    __nv_bfloat16 *p_aval, *p_aom, *p_aop, *p_bw;
    cudaGetSymbolAddress((void**)&p_value, g_value);
    cudaGetSymbolAddress((void**)&p_om_p, g_om_p);
    cudaGetSymbolAddress((void**)&p_bias_om, g_bias_om);
    cudaGetSymbolAddress((void**)&p_aval, g_aval);
    cudaGetSymbolAddress((void**)&p_aom, g_aom);
    cudaGetSymbolAddress((void**)&p_aop, g_aop);
    cudaGetSymbolAddress((void**)&p_bw, g_bw);

    prep_w_kernel<<<dim3(256, 3), 256>>>(om_w, om_b, vp_w, op_w);
    convT_kernel<<<dim3(L / 256, 4, NB), 256>>>(x, p_aval);
    convT_om_kernel<<<dim3(L / 256, 4, NB), 256>>>(x, dw_w, dw_b, p_aom);
    gemm_mma_kernel<<<dim3(2, 32, NB), 256>>>(p_aom, p_bw, p_bias_om, p_om_p, 0);
    gemm_mma_kernel<<<dim3(2, 32, NB), 256>>>(p_aval, p_bw + (size_t)256 * KA, vp_b, p_value, 0);
    sample_kernel<<<dim3(L / 32, G, NB), 256>>>();
    gemm_mma_kernel<<<dim3(2, 32, NB), 256>>>(p_aop, p_bw + (size_t)2 * 256 * KA, p_bias_om, out, 1);
}